// round 17
// baseline (speedup 1.0000x reference)
#include <cuda_runtime.h>

#define NTAGS 64
#define SOS_IDX 1
#define EOS_IDX 2
#define REF_TAG 3
#define MAXB 1024
#define NWORKER 148

__device__ int g_len[MAXB];
__device__ int g_order[MAXB];
__device__ int g_p1;    // phase-1 (lengths) completion counter
__device__ int g_p2;    // phase-2 (ranks) completion counter
__device__ int g_wq;    // work-queue counter
__device__ int g_exit;  // exit counter (last CTA resets everything)

static __device__ __forceinline__ unsigned long long pk2(float x, float y) {
    unsigned long long r;
    asm("mov.b64 %0, {%1, %2};" : "=l"(r) : "f"(x), "f"(y));
    return r;
}
static __device__ __forceinline__ void upk2(unsigned long long a, float &x, float &y) {
    asm("mov.b64 {%0, %1}, %2;" : "=f"(x), "=f"(y) : "l"(a));
}
static __device__ __forceinline__ unsigned long long fma2(unsigned long long a,
                                                          unsigned long long b,
                                                          unsigned long long c) {
    unsigned long long d;
    asm("fma.rn.f32x2 %0, %1, %2, %3;" : "=l"(d) : "l"(a), "l"(b), "l"(c));
    return d;
}
static __device__ __forceinline__ unsigned long long add2(unsigned long long a,
                                                          unsigned long long b) {
    unsigned long long d;
    asm("add.rn.f32x2 %0, %1, %2;" : "=l"(d) : "l"(a), "l"(b));
    return d;
}

__global__ void __launch_bounds__(NTAGS) crf_fused_kernel(
    const float* __restrict__ h, const float* __restrict__ mask,
    const float* __restrict__ trans, float* __restrict__ out, int T, int B)
{
    const int i = threadIdx.x;          // one thread per tag
    const int warp = i >> 5;
    const int lane = i & 31;
    const int blk = blockIdx.x;

    __shared__ __align__(16) float sh_u[2][NTAGS];
    __shared__ float sh_red[2];
    __shared__ int sh_ired[2];
    __shared__ int sh_idx;

    // ---- phase 1: lengths for my rows (mask is a prefix of ones) ----
    for (int b = blk; b < B; b += NWORKER) {
        const float4* m4 = reinterpret_cast<const float4*>(mask + (size_t)b * T);
        const int n4 = T >> 2;
        float msum = 0.0f;
        for (int k = i; k < n4; k += NTAGS) {
            float4 v = m4[k];
            msum += (v.x + v.y) + (v.z + v.w);
        }
        #pragma unroll
        for (int o = 16; o > 0; o >>= 1) msum += __shfl_xor_sync(0xffffffffu, msum, o);
        if (lane == 0) sh_red[warp] = msum;
        __syncthreads();
        if (i == 0) g_len[b] = (int)(sh_red[0] + sh_red[1] + 0.5f);
        __syncthreads();
    }
    __threadfence();
    if (i == 0) atomicAdd(&g_p1, 1);

    // ---- E2 setup (overlaps other blocks finishing phase 1) ----
    // E[i][j] = exp(trans[i][j]) packed as f32x2 (constant over all chains).
    // exp(-10000) underflows to exactly 0 -> masked transitions vanish.
    unsigned long long E2[NTAGS / 2];
    {
        const float4* tr = reinterpret_cast<const float4*>(trans + i * NTAGS);
        #pragma unroll
        for (int k = 0; k < NTAGS / 4; k++) {
            float4 t4 = tr[k];
            E2[2 * k]     = pk2(__expf(t4.x), __expf(t4.y));
            E2[2 * k + 1] = pk2(__expf(t4.z), __expf(t4.w));
        }
    }
    const float eeos = __expf(trans[EOS_IDX * NTAGS + i]);

    // ---- wait for all lengths (all 148 CTAs are wave-1 resident) ----
    if (i == 0) {
        while (atomicAdd(&g_p1, 0) < NWORKER) __nanosleep(64);
    }
    __syncthreads();
    __threadfence();

    // ---- phase 2: LPT rank (replaces sort): rank = #chains strictly ahead ----
    for (int b = blk; b < B; b += NWORKER) {
        const int lb = g_len[b];
        int cnt = 0;
        for (int b2 = i; b2 < B; b2 += NTAGS) {
            const int l2 = g_len[b2];
            cnt += (l2 > lb || (l2 == lb && b2 < b)) ? 1 : 0;
        }
        #pragma unroll
        for (int o = 16; o > 0; o >>= 1) cnt += __shfl_xor_sync(0xffffffffu, cnt, o);
        if (lane == 0) sh_ired[warp] = cnt;
        __syncthreads();
        if (i == 0) g_order[sh_ired[0] + sh_ired[1]] = b;
        __syncthreads();
    }
    __threadfence();
    if (i == 0) {
        atomicAdd(&g_p2, 1);
        while (atomicAdd(&g_p2, 0) < NWORKER) __nanosleep(64);
    }
    __syncthreads();
    __threadfence();

    // ---- work loop: longest chains first (R12 body, verbatim) ----
    for (;;) {
        if (i == 0) sh_idx = atomicAdd(&g_wq, 1);
        __syncthreads();
        const int idx = sh_idx;
        if (idx >= B) break;            // uniform exit
        const int b = g_order[idx];
        const int len = g_len[b];
        const float* hb = h + (size_t)b * T * NTAGS + i;

        // raw prefetch buffers (depth 4)
        float rawh[4];
        #pragma unroll
        for (int k = 0; k < 4; k++) {
            int tp = (k < T) ? k : (T - 1);
            rawh[k] = hb[(size_t)tp * NTAGS];
        }

        // U(-1): 1 at SOS, 0 elsewhere.
        sh_u[0][i] = (i == SOS_IDX) ? 1.0f : 0.0f;
        float myu = (i == SOS_IDX) ? 1.0f : 0.0f;
        int Esum = 0;
        float ehcur = __expf(rawh[0]);  // exp computed one full step ahead
        __syncthreads();

        #pragma unroll 4
        for (int t = 0; t < len; t++) {
            const float* up = sh_u[t & 1];
            float* un = sh_u[(t + 1) & 1];
            const float4* pv = reinterpret_cast<const float4*>(up);

            // issue all shared loads first: renorm scalar + 16 LDS.128
            const unsigned int ub = __float_as_uint(up[REF_TAG]);
            float4 pa[16];
            #pragma unroll
            for (int k = 0; k < 16; k++) pa[k] = pv[k];

            // independent work overlapping LDS latency: h(t+4), exp(t+1)
            int tp = t + 4;
            tp = (tp < T) ? tp : (T - 1);
            float fresh = hb[(size_t)tp * NTAGS];
            float ehnext = __expf(rawh[(t + 1) & 3]);   // loaded at t-3
            rawh[t & 3] = fresh;
            const float eh = ehcur;
            ehcur = ehnext;

            // exact power-of-two renormalizer (ALU-only, off the dot path)
            int e = (int)((ub >> 23) & 0xffu) - 127;
            e = (ub == 0u) ? 0 : e;         // t==0: uref is exactly 0
            const float scale = __uint_as_float((unsigned)(127 - e) << 23);
            Esum += e;
            const float es = eh * scale;

            // w_i = dot(E_row_i, U_prev): 32 fma2, 8 independent accumulators
            unsigned long long acc[8];
            #pragma unroll
            for (int k = 0; k < 16; k++) {
                const int a0 = (k & 3) * 2;
                unsigned long long lo = fma2(E2[2 * k],     pk2(pa[k].x, pa[k].y),
                                             (k < 4) ? 0ull : acc[a0]);
                unsigned long long hi = fma2(E2[2 * k + 1], pk2(pa[k].z, pa[k].w),
                                             (k < 4) ? 0ull : acc[a0 + 1]);
                acc[a0] = lo; acc[a0 + 1] = hi;
            }
            unsigned long long sA = add2(add2(add2(acc[0], acc[2]), add2(acc[4], acc[6])),
                                         add2(add2(acc[1], acc[3]), add2(acc[5], acc[7])));
            float vx, vy;
            upk2(sA, vx, vy);
            const float w = vx + vy;

            const float u = es * w;         // U_i(t)
            un[i] = u;
            myu = u;
            __syncthreads();                // single barrier per step
        }

        // out[b] = Esum*ln2 + log( sum_i U_i * exp(trans[EOS,i]) )
        float term = myu * eeos;
        #pragma unroll
        for (int o = 16; o > 0; o >>= 1) term += __shfl_xor_sync(0xffffffffu, term, o);
        __syncthreads();
        if (lane == 0) sh_red[warp] = term;
        __syncthreads();
        if (i == 0) {
            out[b] = (float)Esum * 0.6931471805599453f + __logf(sh_red[0] + sh_red[1]);
        }
        __syncthreads();                    // protect sh_u/sh_red before next chain
    }

    // ---- exit: last CTA resets counters for the next graph replay ----
    // Safe: reset needs all 148 CTAs to reach here, which requires all of
    // them to have passed both spins and drained the queue.
    if (i == 0) {
        __threadfence();
        int n = atomicAdd(&g_exit, 1);
        if (n == NWORKER - 1) {
            g_p1 = 0; g_p2 = 0; g_wq = 0; g_exit = 0;
            __threadfence();
        }
    }
}

extern "C" void kernel_launch(void* const* d_in, const int* in_sizes, int n_in,
                              void* d_out, int out_size) {
    const float* h     = (const float*)d_in[0];   // [B, T, 64]
    const float* mask  = (const float*)d_in[1];   // [B, T]
    const float* trans = (const float*)d_in[2];   // [64, 64]
    float* out = (float*)d_out;                   // [B]
    const int B = out_size;
    const int T = in_sizes[1] / B;
    crf_fused_kernel<<<NWORKER, NTAGS>>>(h, mask, trans, out, T, B);
}